// round 5
// baseline (speedup 1.0000x reference)
#include <cuda_runtime.h>
#include <cuda_fp16.h>
#include <cstdint>
#include <cstddef>

#define EPS 1e-5f
#define KC 25          // k-slices per warp cached in smem (of 64)
#define NTHREADS 256

// ---------------- device globals (scratch; no allocations allowed) ----------------
// packed recurrent weights: [m][b][r][k=512][rowlocal=256] fp16
//   m=0: whh0 ; m=1: wih1+whh1
__device__ __half g_warr[2u * 16u * 8u * 512u * 256u];                 // 67.1 MB
__device__ float g_gi0[16u * 256u * 2048u];                            // 33.5 MB: wih0@x + bias0
__device__ float g_bias0[16u * 2048u];
__device__ float g_bias1[16u * 2048u];

// ---------------- PTX helpers ----------------
__device__ __forceinline__ uint32_t smem_u32(const void* p) {
    uint32_t a;
    asm("{ .reg .u64 t; cvta.to.shared.u64 t, %1; cvt.u32.u64 %0, t; }" : "=r"(a) : "l"(p));
    return a;
}
__device__ __forceinline__ uint32_t mapa_u32(uint32_t addr, uint32_t rank) {
    uint32_t r; asm("mapa.shared::cluster.u32 %0, %1, %2;" : "=r"(r) : "r"(addr), "r"(rank));
    return r;
}
__device__ __forceinline__ float2 ld_dsmem_f2(uint32_t addr) {
    float2 v;
    asm volatile("ld.shared::cluster.v2.f32 {%0,%1}, [%2];" : "=f"(v.x), "=f"(v.y) : "r"(addr));
    return v;
}
__device__ __forceinline__ float ld_dsmem_f(uint32_t addr) {
    float v; asm volatile("ld.shared::cluster.f32 %0, [%1];" : "=f"(v) : "r"(addr));
    return v;
}
__device__ __forceinline__ uint32_t ctarank() {
    uint32_t r; asm("mov.u32 %0, %%cluster_ctarank;" : "=r"(r)); return r;
}
#define CLUSTER_SYNC() do { \
    __syncthreads(); \
    asm volatile("barrier.cluster.arrive.aligned;" ::: "memory"); \
    asm volatile("barrier.cluster.wait.aligned;"   ::: "memory"); \
} while (0)

// ---------------- K0: bias precompute ----------------
__global__ void k0_init(const float* __restrict__ bih0, const float* __restrict__ bhh0,
                        const float* __restrict__ bih1, const float* __restrict__ bhh1) {
    int i = blockIdx.x * blockDim.x + threadIdx.x;   // 128*256 = 32768 = 16*2048
    g_bias0[i] = bih0[i] + bhh0[i];
    g_bias1[i] = bih1[i] + bhh1[i];
}

// ---------------- K1: pack/transpose recurrent weights to fp16 [k][row] ----------------
// grid (8 ktile, 8 rank, 32 = m*16+b), 256 threads; tile = 64 k x 256 rows
__global__ void k1_pack(const float* __restrict__ whh0, const float* __restrict__ wih1,
                        const float* __restrict__ whh1) {
    __shared__ __align__(16) __half sm[64 * 264];
    int kt = blockIdx.x, r = blockIdx.y;
    int mb = blockIdx.z; int m = mb >> 4, b = mb & 15;
    int tid = threadIdx.x;
    int grow = ((tid >> 6) << 9) + (r << 6) + (tid & 63);  // global gate-row
    int k0 = kt * 64;
    const float* s0 = (m == 0 ? whh0 : wih1) + ((size_t)(b * 2048 + grow) * 512 + k0);
    const float* s1 = whh1 + ((size_t)(b * 2048 + grow) * 512 + k0);
#pragma unroll
    for (int q = 0; q < 16; q++) {
        float4 v = *(const float4*)(s0 + q * 4);
        if (m) {
            float4 u = *(const float4*)(s1 + q * 4);
            v.x += u.x; v.y += u.y; v.z += u.z; v.w += u.w;
        }
        sm[(q * 4 + 0) * 264 + tid] = __float2half(v.x);
        sm[(q * 4 + 1) * 264 + tid] = __float2half(v.y);
        sm[(q * 4 + 2) * 264 + tid] = __float2half(v.z);
        sm[(q * 4 + 3) * 264 + tid] = __float2half(v.w);
    }
    __syncthreads();
    __half* out = &g_warr[(((size_t)mb) * 8u + r) * 512u * 256u + (size_t)k0 * 256u];
    int kk = tid >> 2, rb = (tid & 3) * 64;
    const uint4* src = (const uint4*)(sm + kk * 264 + rb);
    uint4* dst = (uint4*)(out + kk * 256 + rb);
#pragma unroll
    for (int q = 0; q < 8; q++) dst[q] = src[q];
}

// ---------------- K2: precompute gi0[b][t][row] = wih0@x_t + bias0 ----------------
__global__ void k2_gemm(const float* __restrict__ wih0, const float* __restrict__ x) {
    __shared__ float As[64][17];
    __shared__ float Bs[16][65];
    int rt = blockIdx.x, tt = blockIdx.y, b = blockIdx.z;
    int row0 = rt * 64, t0 = tt * 64;
    int tid = threadIdx.x;
    int lm = tid >> 2, kq = tid & 3;
    const float* Ap = wih0 + ((size_t)(b * 2048 + row0 + lm) * 512 + kq * 4);
    const float* Bp = x + ((size_t)(b * 256 + t0 + lm) * 512 + kq * 4);
    int ty = tid >> 4, tx = tid & 15;
    float C[4][4];
#pragma unroll
    for (int i = 0; i < 4; i++)
#pragma unroll
        for (int j = 0; j < 4; j++) C[i][j] = 0.f;

    for (int kc = 0; kc < 512; kc += 16) {
        float4 a4 = *(const float4*)(Ap + kc);
        float4 b4 = *(const float4*)(Bp + kc);
        As[lm][kq * 4 + 0] = a4.x; As[lm][kq * 4 + 1] = a4.y;
        As[lm][kq * 4 + 2] = a4.z; As[lm][kq * 4 + 3] = a4.w;
        Bs[kq * 4 + 0][lm] = b4.x; Bs[kq * 4 + 1][lm] = b4.y;
        Bs[kq * 4 + 2][lm] = b4.z; Bs[kq * 4 + 3][lm] = b4.w;
        __syncthreads();
#pragma unroll
        for (int kk = 0; kk < 16; kk++) {
            float a[4], bb[4];
#pragma unroll
            for (int i = 0; i < 4; i++) a[i] = As[ty * 4 + i][kk];
#pragma unroll
            for (int j = 0; j < 4; j++) bb[j] = Bs[kk][tx * 4 + j];
#pragma unroll
            for (int i = 0; i < 4; i++)
#pragma unroll
                for (int j = 0; j < 4; j++) C[i][j] += a[i] * bb[j];
        }
        __syncthreads();
    }
    float4 bias = *(const float4*)&g_bias0[b * 2048 + row0 + ty * 4];
#pragma unroll
    for (int j = 0; j < 4; j++) {
        float4 vo;
        vo.x = C[0][j] + bias.x; vo.y = C[1][j] + bias.y;
        vo.z = C[2][j] + bias.z; vo.w = C[3][j] + bias.w;
        *(float4*)&g_gi0[((size_t)(b * 256 + t0 + tx * 4 + j)) * 2048 + row0 + ty * 4] = vo;
    }
}

// ---------------- K3: persistent recurrent kernel, cluster of 8 per batch ----------------
struct Smem {
    __half wcache[2 * 8 * KC * 256];   // [m][warp][kk][row256]  204800 B
    float h_s[512];
    float red[8][256];
    float gp[256];
    float act[256];
    float c_s[64];
    float o_s[64];
    float wpart[8][2];
    float h_pub[64];
    float gw[2][64], gb[2][64];
    float2 stats[4];     // own gate partials (S,Q)
    float2 stot[4];      // cluster-total gate stats
    float2 cstat;        // own c partial
    float2 ctot;         // cluster-total c stats
};

__global__ void __launch_bounds__(NTHREADS, 1) __cluster_dims__(8, 1, 1)
k3_lstm(const float* __restrict__ ln_w, const float* __restrict__ ln_b, float* __restrict__ y) {
    extern __shared__ __align__(16) unsigned char smem_raw[];
    Smem* S = (Smem*)smem_raw;
    uint32_t sbase = smem_u32(smem_raw);
    const uint32_t off_stats = (uint32_t)offsetof(Smem, stats);
    const uint32_t off_cstat = (uint32_t)offsetof(Smem, cstat);
    const uint32_t off_hpub  = (uint32_t)offsetof(Smem, h_pub);

    int g = blockIdx.x >> 3;
    int r = (int)ctarank();
    int tid = threadIdx.x, warp = tid >> 5, lane = tid & 31;
    int gate = tid >> 6, jl = tid & 63;

    // ---- prologue: init + load weight cache into smem ----
    S->h_s[tid] = 0.f; S->h_s[tid + 256] = 0.f;
    if (tid < 64) S->c_s[tid] = 0.f;
    if (tid < 128) {
        int l = tid >> 6, jj = tid & 63;
        S->gw[l][jj] = ln_w[l * 512 + r * 64 + jj];
        S->gb[l][jj] = ln_b[l * 512 + r * 64 + jj];
    }
    {
        const uint4* W0 = (const uint4*)&g_warr[(((size_t)(0 * 16 + g)) * 8u + r) * 512u * 256u];
        const uint4* W1 = (const uint4*)&g_warr[(((size_t)(1 * 16 + g)) * 8u + r) * 512u * 256u];
        uint4* dst = (uint4*)S->wcache;
        const int total = 2 * 8 * KC * 32;           // uint4 count
        for (int i = tid; i < total; i += NTHREADS) {
            int m  = i / (8 * KC * 32);
            int rm = i - m * (8 * KC * 32);
            int w  = rm / (KC * 32);
            int r2 = rm - w * (KC * 32);
            int kk = r2 >> 5;
            int j  = r2 & 31;
            const uint4* src = (m ? W1 : W0) + (size_t)(w * 64 + kk) * 32 + j;
            dst[i] = __ldcg(src);
        }
    }
    __syncthreads();

    for (int t = 0; t < 256; t++) {
        for (int l = 0; l < 2; l++) {
            // ---- matvec: 256 rows x K=512; warp w owns k-range [64w,64w+64) ----
            const __half* W = &g_warr[(((size_t)(l * 16 + g)) * 8u + r) * 512u * 256u];
            const uint4* Wp = (const uint4*)(W) + (size_t)warp * 2048 + lane;
            const uint4* Sc = (const uint4*)S->wcache + (size_t)(l * 8 + warp) * (KC * 32) + lane;
            float acc[8];
#pragma unroll
            for (int i = 0; i < 8; i++) acc[i] = 0.f;
            // cached part (smem)
#pragma unroll 5
            for (int kk = 0; kk < KC; kk++) {
                uint4 w4 = Sc[kk * 32];
                float hk = S->h_s[warp * 64 + kk];
                const __half2* hp = (const __half2*)&w4;
                float2 f0 = __half22float2(hp[0]);
                float2 f1 = __half22float2(hp[1]);
                float2 f2 = __half22float2(hp[2]);
                float2 f3 = __half22float2(hp[3]);
                acc[0] += hk * f0.x; acc[1] += hk * f0.y;
                acc[2] += hk * f1.x; acc[3] += hk * f1.y;
                acc[4] += hk * f2.x; acc[5] += hk * f2.y;
                acc[6] += hk * f3.x; acc[7] += hk * f3.y;
            }
            // streamed part (L2)
#pragma unroll 13
            for (int kk = KC; kk < 64; kk++) {
                uint4 w4 = __ldcg(Wp + (size_t)kk * 32);
                float hk = S->h_s[warp * 64 + kk];
                const __half2* hp = (const __half2*)&w4;
                float2 f0 = __half22float2(hp[0]);
                float2 f1 = __half22float2(hp[1]);
                float2 f2 = __half22float2(hp[2]);
                float2 f3 = __half22float2(hp[3]);
                acc[0] += hk * f0.x; acc[1] += hk * f0.y;
                acc[2] += hk * f1.x; acc[3] += hk * f1.y;
                acc[4] += hk * f2.x; acc[5] += hk * f2.y;
                acc[6] += hk * f3.x; acc[7] += hk * f3.y;
            }
            *(float4*)&S->red[warp][lane * 8]     = make_float4(acc[0], acc[1], acc[2], acc[3]);
            *(float4*)&S->red[warp][lane * 8 + 4] = make_float4(acc[4], acc[5], acc[6], acc[7]);
            __syncthreads();
            float v = 0.f;
#pragma unroll
            for (int w = 0; w < 8; w++) v += S->red[w][tid];
            int rowg = (gate << 9) + (r << 6) + jl;
            v += (l == 0) ? __ldcg(&g_gi0[((size_t)(g * 256 + t)) * 2048 + rowg])
                          : g_bias1[g * 2048 + rowg];
            S->gp[tid] = v;

            // ---- local gate-stat partials ----
            float s = v, q = v * v;
#pragma unroll
            for (int o = 16; o > 0; o >>= 1) {
                s += __shfl_xor_sync(0xffffffffu, s, o);
                q += __shfl_xor_sync(0xffffffffu, q, o);
            }
            if (lane == 0) { S->wpart[warp][0] = s; S->wpart[warp][1] = q; }
            __syncthreads();
            if (tid < 4) {
                S->stats[tid] = make_float2(S->wpart[2 * tid][0] + S->wpart[2 * tid + 1][0],
                                            S->wpart[2 * tid][1] + S->wpart[2 * tid + 1][1]);
            }
            CLUSTER_SYNC();   // sync #1: gate partials published

            // ---- gather cluster gate stats via DSMEM (warp 0) ----
            if (warp == 0) {
                int gg = lane >> 3, rr = lane & 7;
                float2 p = ld_dsmem_f2(mapa_u32(sbase + off_stats + gg * 8, rr));
                float ss = p.x, qq = p.y;
                ss += __shfl_xor_sync(0xffffffffu, ss, 1); qq += __shfl_xor_sync(0xffffffffu, qq, 1);
                ss += __shfl_xor_sync(0xffffffffu, ss, 2); qq += __shfl_xor_sync(0xffffffffu, qq, 2);
                ss += __shfl_xor_sync(0xffffffffu, ss, 4); qq += __shfl_xor_sync(0xffffffffu, qq, 4);
                if (rr == 0) S->stot[gg] = make_float2(ss, qq);
            }
            __syncthreads();

            // ---- LN per gate + activation ----
            {
                float2 T = S->stot[gate];
                float mean = T.x * (1.f / 512.f);
                float var  = T.y * (1.f / 512.f) - mean * mean;
                float rstd = rsqrtf(var + EPS);
                float xn = (S->gp[tid] - mean) * rstd * S->gw[l][jl] + S->gb[l][jl];
                float a = (gate == 2) ? tanhf(xn) : (1.f / (1.f + __expf(-xn)));
                S->act[tid] = a;
            }
            __syncthreads();

            // ---- c update + c-stat partial (threads 0..63) ----
            float cn = 0.f;
            if (tid < 64) {
                cn = S->act[64 + tid] * S->c_s[tid] + S->act[tid] * S->act[128 + tid];
                S->c_s[tid] = cn;
                S->o_s[tid] = S->act[192 + tid];
            }
            if (warp < 2) {
                float s2 = cn, q2 = cn * cn;
#pragma unroll
                for (int o = 16; o > 0; o >>= 1) {
                    s2 += __shfl_xor_sync(0xffffffffu, s2, o);
                    q2 += __shfl_xor_sync(0xffffffffu, q2, o);
                }
                if (lane == 0) { S->wpart[warp][0] = s2; S->wpart[warp][1] = q2; }
            }
            __syncthreads();
            if (tid == 0) {
                S->cstat = make_float2(S->wpart[0][0] + S->wpart[1][0],
                                       S->wpart[0][1] + S->wpart[1][1]);
            }
            CLUSTER_SYNC();   // sync #2: c partials published

            // ---- gather cluster c stats (warp 0, lanes 0..7) ----
            if (warp == 0) {
                float2 p = (lane < 8) ? ld_dsmem_f2(mapa_u32(sbase + off_cstat, lane & 7))
                                      : make_float2(0.f, 0.f);
                float ss = p.x, qq = p.y;
                ss += __shfl_xor_sync(0xffffffffu, ss, 1); qq += __shfl_xor_sync(0xffffffffu, qq, 1);
                ss += __shfl_xor_sync(0xffffffffu, ss, 2); qq += __shfl_xor_sync(0xffffffffu, qq, 2);
                ss += __shfl_xor_sync(0xffffffffu, ss, 4); qq += __shfl_xor_sync(0xffffffffu, qq, 4);
                if (lane == 0) S->ctot = make_float2(ss, qq);
            }
            __syncthreads();

            // ---- LN(c), h update, publish ----
            if (tid < 64) {
                float2 T = S->ctot;
                float mean = T.x * (1.f / 512.f);
                float var  = T.y * (1.f / 512.f) - mean * mean;
                float rstd = rsqrtf(var + EPS);
                float hv = S->o_s[tid] * tanhf((S->c_s[tid] - mean) * rstd * S->gw[l][tid] + S->gb[l][tid]);
                S->h_pub[tid] = hv;
                if (l == 1) y[((size_t)(g * 256 + t)) * 512 + r * 64 + tid] = hv;
            }
            CLUSTER_SYNC();   // sync #3: h published

            // ---- gather full h from cluster peers ----
            {
                uint32_t a0 = mapa_u32(sbase + off_hpub + (uint32_t)(tid & 63) * 4u, (uint32_t)(tid >> 6));
                uint32_t a1 = mapa_u32(sbase + off_hpub + (uint32_t)(tid & 63) * 4u, (uint32_t)((tid + 256) >> 6));
                S->h_s[tid]       = ld_dsmem_f(a0);
                S->h_s[tid + 256] = ld_dsmem_f(a1);
            }
            __syncthreads();
        }
    }
}

// ---------------- launcher ----------------
extern "C" void kernel_launch(void* const* d_in, const int* in_sizes, int n_in,
                              void* d_out, int out_size) {
    (void)in_sizes; (void)n_in; (void)out_size;
    const float* x    = (const float*)d_in[0];
    const float* wih0 = (const float*)d_in[1];
    const float* whh0 = (const float*)d_in[2];
    const float* bih0 = (const float*)d_in[3];
    const float* bhh0 = (const float*)d_in[4];
    const float* wih1 = (const float*)d_in[5];
    const float* whh1 = (const float*)d_in[6];
    const float* bih1 = (const float*)d_in[7];
    const float* bhh1 = (const float*)d_in[8];
    const float* ln_w = (const float*)d_in[9];
    const float* ln_b = (const float*)d_in[10];
    float* y = (float*)d_out;

    static int smem_set = 0;
    if (!smem_set) {
        cudaFuncSetAttribute(k3_lstm, cudaFuncAttributeMaxDynamicSharedMemorySize,
                             (int)sizeof(Smem));
        smem_set = 1;
    }

    k0_init<<<128, 256>>>(bih0, bhh0, bih1, bhh1);
    k1_pack<<<dim3(8, 8, 32), 256>>>(whh0, wih1, whh1);
    k2_gemm<<<dim3(32, 4, 16), 256>>>(wih0, x);
    k3_lstm<<<128, NTHREADS, sizeof(Smem)>>>(ln_w, ln_b, y);
}